// round 4
// baseline (speedup 1.0000x reference)
#include <cuda_runtime.h>
#include <cstdint>

// path_generator_GAD: N=131072 paths, T=251 (250 sequential steps).
// s_{t+1} = s + (b0 + b1*s)*dt + (a0 + a1*max(s,0))^g * Z*sqrt(dt)
//
// R4: same cp.async double-buffered tile pipeline as R3, but tile shrunk
// TW 16->8 and WPB 8->4 so smem/block = 55.3KB -> 4 blocks/SM = 16 warps/SM
// (R3 was smem-strangled to 8 warps/SM -> latency bound at 9% issue).

#define TSTEPS   251
#define DT_F     0.004f
#define SQRT_DT  0.063245553203367586f
#define S0_F     100.0f
#define TW       8                        // timesteps per tile
#define TSTRIDE  9                        // padded smem row stride (gcd(9,32)=1)
#define WPB      4                        // warps per block
#define NTILES   32                       // ceil(250/8)
#define ARRF     (32 * TSTRIDE)           // floats per array tile (288)
#define WARPF    (6 * ARRF)               // floats per warp per buffer (1728)
#define BUFF     (WPB * WARPF)            // floats per buffer, all warps (6912)

__device__ __forceinline__ void cp4(unsigned int saddr, const float* g) {
    asm volatile("cp.async.ca.shared.global [%0], [%1], 4;" :: "r"(saddr), "l"(g));
}
__device__ __forceinline__ void cp_commit() {
    asm volatile("cp.async.commit_group;");
}
__device__ __forceinline__ void cp_wait1() {
    asm volatile("cp.async.wait_group 1;");
}

__global__ __launch_bounds__(WPB * 32, 4)
void gad_kernel(const float* __restrict__ Z,
                const float* __restrict__ Ua0,
                const float* __restrict__ Ua1,
                const float* __restrict__ Ub0,
                const float* __restrict__ Ub1,
                const float* __restrict__ Ug,
                float* __restrict__ out)
{
    extern __shared__ float smem[];
    const int warp = threadIdx.x >> 5;
    const int lane = threadIdx.x & 31;
    const int tcol = lane & 7;           // timestep within tile (load/store role)
    const int prow = lane >> 3;          // 0..3: which row group this lane loads
    const int pBase = (blockIdx.x * WPB + warp) << 5;

    const unsigned int smem_u32 = (unsigned int)__cvta_generic_to_shared(smem);

    out[(pBase + lane) * TSTEPS] = S0_F;  // column 0 = S0

    // issue all 6 arrays' tile k into buffer b (async), then commit a group
#define ISSUE_TILE(k, b)                                                     \
    {                                                                        \
        const int t0_ = 1 + (k) * TW;                                        \
        if (t0_ + tcol < TSTEPS) {                                           \
            const unsigned int sw =                                          \
                smem_u32 + (unsigned int)(((b) * BUFF + warp * WARPF) * 4);  \
            _Pragma("unroll")                                                \
            for (int r = 0; r < 32; r += 4) {                                \
                const int row_ = r + prow;                                   \
                const int gi_  = (pBase + row_) * TSTEPS + t0_ + tcol;       \
                const unsigned int so =                                      \
                    sw + (unsigned int)((row_ * TSTRIDE + tcol) * 4);        \
                cp4(so + 0u * (ARRF * 4), Z   + gi_);                        \
                cp4(so + 1u * (ARRF * 4), Ua0 + gi_);                        \
                cp4(so + 2u * (ARRF * 4), Ua1 + gi_);                        \
                cp4(so + 3u * (ARRF * 4), Ub0 + gi_);                        \
                cp4(so + 4u * (ARRF * 4), Ub1 + gi_);                        \
                cp4(so + 5u * (ARRF * 4), Ug  + gi_);                        \
            }                                                                \
        }                                                                    \
        cp_commit();                                                         \
    }

    // prime the 2-deep pipeline
    ISSUE_TILE(0, 0)
    ISSUE_TILE(1, 1)

    float s = S0_F;

    for (int k = 0; k < NTILES; ++k) {
        const int buf = k & 1;
        const int t0  = 1 + k * TW;
        const int w   = min(TW, TSTEPS - t0);   // 8 except last tile (2)

        cp_wait1();          // tile k complete (<=1 group pending)
        __syncwarp();        // make peers' cp.async data visible

        float* B   = smem + buf * BUFF + warp * WARPF;
        float* tZ  = B;
        float* tA0 = B + 1 * ARRF;
        float* tA1 = B + 2 * ARRF;
        float* tB0 = B + 3 * ARRF;
        float* tB1 = B + 4 * ARRF;
        float* tG  = B + 5 * ARRF;

        const int sb = lane * TSTRIDE;

#define GAD_STEP(J)                                                   \
        {                                                             \
            const int si = sb + (J);                                  \
            float a0 = fmaf(tA0[si], 0.10f, 0.05f);                   \
            float a1 = fmaf(tA1[si], 0.20f, 0.10f);                   \
            float b0 = tB0[si] * 0.05f;                               \
            float b1 = tB1[si] * 0.10f;                               \
            float g  = fmaf(tG[si], 0.20f, 0.80f);                    \
            float zt = tZ[si] * SQRT_DT;                              \
            float base = fmaf(a1, fmaxf(s, 0.0f), a0);                \
            s = fmaf(fmaf(b1, s, b0), DT_F, s) + __powf(base, g) * zt;\
            tZ[si] = s;  /* stage output into consumed Z slot */      \
        }

        if (w == TW) {
            #pragma unroll
            for (int j = 0; j < TW; ++j) GAD_STEP(j)
        } else {
            for (int j = 0; j < w; ++j) GAD_STEP(j)
        }
#undef GAD_STEP

        __syncwarp();
        // coalesced write-back from the staged tZ tile
        if (tcol < w) {
            #pragma unroll
            for (int r = 0; r < 32; r += 4) {
                const int row = r + prow;
                out[(pBase + row) * TSTEPS + t0 + tcol] =
                    tZ[row * TSTRIDE + tcol];
            }
        }
        __syncwarp();        // all lanes done reading buf before refill

        if (k + 2 < NTILES) {
            ISSUE_TILE(k + 2, buf)
        } else {
            cp_commit();     // keep group accounting aligned for cp_wait1
        }
    }
#undef ISSUE_TILE
}

extern "C" void kernel_launch(void* const* d_in, const int* in_sizes, int n_in,
                              void* d_out, int out_size)
{
    const float* Z   = (const float*)d_in[0];
    const float* Ua0 = (const float*)d_in[1];
    const float* Ua1 = (const float*)d_in[2];
    const float* Ub0 = (const float*)d_in[3];
    const float* Ub1 = (const float*)d_in[4];
    const float* Ug  = (const float*)d_in[5];
    float* out = (float*)d_out;

    const int N = in_sizes[0] / TSTEPS;          // 131072
    const int pathsPerBlock = WPB * 32;          // 128
    const int blocks = (N + pathsPerBlock - 1) / pathsPerBlock;   // 1024

    const size_t smem = (size_t)2 * BUFF * sizeof(float);   // 55296 B
    cudaFuncSetAttribute(gad_kernel, cudaFuncAttributeMaxDynamicSharedMemorySize, (int)smem);

    gad_kernel<<<blocks, pathsPerBlock, smem>>>(Z, Ua0, Ua1, Ub0, Ub1, Ug, out);
}

// round 5
// speedup vs baseline: 2.0346x; 2.0346x over previous
#include <cuda_runtime.h>
#include <cstdint>

// path_generator_GAD: N=131072 paths, T=251 (250 sequential steps).
// s_{t+1} = s + (b0 + b1*s)*dt + (a0 + a1*max(s,0))^g * Z*sqrt(dt)
//
// R5: block-cooperative tiles with 16B cp.async.cg.
//  - block = 128 threads = 128 paths; tile = [128 rows x 8 steps] per array
//  - per row: 16B-aligned 48B window (RW=12 floats), slack 0..3 absorbed
//    by per-row offset (row stride 1004B is only 4B aligned)
//  - double-buffered (73.7KB smem) -> 3 blocks/SM, cp.async.wait_group(1)
//  - last two tiles use exact 4B copies (avoid tail over-read)

#define TSTEPS 251
#define DT_F   0.004f
#define SQRT_DT 0.063245553203367586f
#define S0_F   100.0f
#define TW     8
#define RW     12                 // smem floats per row (16B multiple)
#define NROWS  128                // paths per block
#define NTILES 32
#define ARRF   (NROWS * RW)       // 1536 floats per array tile
#define BUFF   (6 * ARRF)         // 9216 floats per stage

__device__ __forceinline__ void cp16(unsigned sa, const float* g) {
    asm volatile("cp.async.cg.shared.global [%0], [%1], 16;" :: "r"(sa), "l"(g));
}
__device__ __forceinline__ void cp4(unsigned sa, const float* g) {
    asm volatile("cp.async.ca.shared.global [%0], [%1], 4;" :: "r"(sa), "l"(g));
}
__device__ __forceinline__ void cp_commit() {
    asm volatile("cp.async.commit_group;");
}
__device__ __forceinline__ void cp_wait1() {
    asm volatile("cp.async.wait_group 1;");
}

__global__ void __launch_bounds__(NROWS, 3)
gad_kernel(const float* __restrict__ Z,
           const float* __restrict__ Ua0,
           const float* __restrict__ Ua1,
           const float* __restrict__ Ub0,
           const float* __restrict__ Ub1,
           const float* __restrict__ Ug,
           float* __restrict__ out)
{
    extern __shared__ float smem[];
    const int tid = threadIdx.x;
    const int pB  = blockIdx.x * NROWS;
    const unsigned sbase = (unsigned)__cvta_generic_to_shared(smem);

    out[(pB + tid) * TSTEPS] = S0_F;   // column 0 = S0

    // ---- 16B-chunk tile issue: tiles k <= 29 (window fully in-bounds) ----
    auto issue16 = [&](int k, int b) {
        const int t0 = 1 + k * TW;
        const unsigned bb = sbase + (unsigned)(b * BUFF) * 4u;
        #pragma unroll
        for (int i = 0; i < 3; ++i) {
            const int c   = tid + i * NROWS;     // flat chunk id, 0..383
            const int row = c / 3;
            const int kk  = c - row * 3;         // chunk within row, 0..2
            const int slack = (t0 - row) & 3;    // (p*251+t0)&3, p=pB+row
            const int gi  = (pB + row) * TSTEPS + t0 - slack + kk * 4;
            const unsigned d = bb + (unsigned)(row * RW + kk * 4) * 4u;
            cp16(d + 0u * (ARRF * 4), Z   + gi);
            cp16(d + 1u * (ARRF * 4), Ua0 + gi);
            cp16(d + 2u * (ARRF * 4), Ua1 + gi);
            cp16(d + 3u * (ARRF * 4), Ub0 + gi);
            cp16(d + 4u * (ARRF * 4), Ub1 + gi);
            cp16(d + 5u * (ARRF * 4), Ug  + gi);
        }
        cp_commit();
    };

    // ---- exact scalar issue for the last two tiles (k=30 w=8, k=31 w=2) ----
    auto issueS = [&](int k, int b) {
        const int t0 = 1 + k * TW;
        const int w  = min(TW, TSTEPS - t0);
        const int sh = (w == 8) ? 3 : 1;
        const int mk = w - 1;
        const unsigned bb = sbase + (unsigned)(b * BUFF) * 4u;
        for (int idx = tid; idx < NROWS * w; idx += NROWS) {
            const int row = idx >> sh;
            const int j   = idx & mk;
            const int slack = (t0 - row) & 3;
            const int gi  = (pB + row) * TSTEPS + t0 + j;
            const unsigned d = bb + (unsigned)(row * RW + slack + j) * 4u;
            cp4(d + 0u * (ARRF * 4), Z   + gi);
            cp4(d + 1u * (ARRF * 4), Ua0 + gi);
            cp4(d + 2u * (ARRF * 4), Ua1 + gi);
            cp4(d + 3u * (ARRF * 4), Ub0 + gi);
            cp4(d + 4u * (ARRF * 4), Ub1 + gi);
            cp4(d + 5u * (ARRF * 4), Ug  + gi);
        }
        cp_commit();
    };

    // prime the 2-deep pipeline
    issue16(0, 0);
    issue16(1, 1);

    float s = S0_F;

    for (int k = 0; k < NTILES; ++k) {
        const int b  = k & 1;
        const int t0 = 1 + k * TW;
        const int w  = min(TW, TSTEPS - t0);

        cp_wait1();           // my tile-k group landed
        __syncthreads();      // => everyone's tile-k group landed

        float* B = smem + b * BUFF;
        const int sb = tid * RW + ((t0 - tid) & 3);   // my row base + slack

#define GAD_STEP(J)                                                     \
        {                                                               \
            const int si = sb + (J);                                    \
            float a0 = fmaf(B[1*ARRF + si], 0.10f, 0.05f);              \
            float a1 = fmaf(B[2*ARRF + si], 0.20f, 0.10f);              \
            float b0 = B[3*ARRF + si] * 0.05f;                          \
            float b1 = B[4*ARRF + si] * 0.10f;                          \
            float g  = fmaf(B[5*ARRF + si], 0.20f, 0.80f);              \
            float zt = B[si] * SQRT_DT;                                 \
            float base = fmaf(a1, fmaxf(s, 0.0f), a0);                  \
            s = fmaf(fmaf(b1, s, b0), DT_F, s) + __powf(base, g) * zt;  \
            B[si] = s;  /* stage result into consumed Z slot */         \
        }
        if (w == TW) {
            #pragma unroll
            for (int j = 0; j < TW; ++j) GAD_STEP(j)
        } else {
            for (int j = 0; j < w; ++j) GAD_STEP(j)
        }
#undef GAD_STEP

        __syncthreads();      // Z-slot staging complete

        // coalesced write-back: 16 lanes x 8 cols covering 128 rows
        {
            const int col = tid & 7;
            const int rg  = tid >> 3;
            if (col < w) {
                #pragma unroll
                for (int i = 0; i < 8; ++i) {
                    const int r = rg + 16 * i;
                    out[(pB + r) * TSTEPS + t0 + col] =
                        B[r * RW + ((t0 - r) & 3) + col];
                }
            }
        }
        __syncthreads();      // buffer fully consumed before refill

        const int kn = k + 2;
        if (kn < NTILES) {
            if (kn <= 29) issue16(kn, b);
            else          issueS(kn, b);
        } else {
            cp_commit();      // keep group accounting aligned
        }
    }
}

extern "C" void kernel_launch(void* const* d_in, const int* in_sizes, int n_in,
                              void* d_out, int out_size)
{
    const float* Z   = (const float*)d_in[0];
    const float* Ua0 = (const float*)d_in[1];
    const float* Ua1 = (const float*)d_in[2];
    const float* Ub0 = (const float*)d_in[3];
    const float* Ub1 = (const float*)d_in[4];
    const float* Ug  = (const float*)d_in[5];
    float* out = (float*)d_out;

    const int N = in_sizes[0] / TSTEPS;               // 131072
    const int blocks = (N + NROWS - 1) / NROWS;       // 1024

    const size_t smem = (size_t)2 * BUFF * sizeof(float);   // 73728 B
    cudaFuncSetAttribute(gad_kernel, cudaFuncAttributeMaxDynamicSharedMemorySize, (int)smem);

    gad_kernel<<<blocks, NROWS, smem>>>(Z, Ua0, Ua1, Ub0, Ub1, Ug, out);
}

// round 7
// speedup vs baseline: 2.3896x; 1.1744x over previous
#include <cuda_runtime.h>
#include <cstdint>

// path_generator_GAD  (N=131072 paths, T=251)
// s' = s + (b0+b1*s)*dt + (a0+a1*max(s,0))^g * Z*sqrt(dt)
//
// R7 = R6 with the deadlock fixed: cp.async.mbarrier.arrive.NOINC
// (default variant bumps the expected-arrival count -> phase never completes).
//  - 1 producer warp: cp.async.cg 16B chunks into 3-stage mbarrier ring
//  - 4 consumer warps: warp w owns rows == w (mod 4) -> warp-uniform slack;
//    smem slot = tid -> 48B lane stride -> conflict-free LDS.128

#define TSTEPS  251
#define DT_F    0.004f
#define SQRT_DT 0.063245553203367586f
#define S0_F    100.0f
#define TW      8
#define RW      12                  // floats per row slot (16B multiple)
#define NROWS   128
#define NTILES  32
#define STAGES  3
#define ARRF    (NROWS * RW)        // 1536 floats per array tile
#define BUFF    (6 * ARRF)          // 9216 floats per stage
#define DATA_OFF 64                 // floats reserved for barriers (256B)

__device__ __forceinline__ void cp16(unsigned sa, const float* g) {
    asm volatile("cp.async.cg.shared.global [%0], [%1], 16;" :: "r"(sa), "l"(g));
}
__device__ __forceinline__ void cp4(unsigned sa, const float* g) {
    asm volatile("cp.async.ca.shared.global [%0], [%1], 4;" :: "r"(sa), "l"(g));
}
__device__ __forceinline__ void mbar_init(unsigned a, unsigned cnt) {
    asm volatile("mbarrier.init.shared.b64 [%0], %1;" :: "r"(a), "r"(cnt));
}
__device__ __forceinline__ void mbar_arrive(unsigned a) {
    asm volatile("mbarrier.arrive.shared.b64 _, [%0];" :: "r"(a) : "memory");
}
__device__ __forceinline__ void cp_arrive_noinc(unsigned a) {
    asm volatile("cp.async.mbarrier.arrive.noinc.shared.b64 [%0];" :: "r"(a) : "memory");
}
__device__ __forceinline__ void mbar_wait(unsigned a, unsigned ph) {
    unsigned done;
    asm volatile(
        "{\n\t.reg .pred p;\n\t"
        "mbarrier.try_wait.parity.acquire.cta.shared::cta.b64 p, [%1], %2;\n\t"
        "selp.b32 %0,1,0,p;\n\t}"
        : "=r"(done) : "r"(a), "r"(ph) : "memory");
    while (!done) {
        asm volatile(
            "{\n\t.reg .pred p;\n\t"
            "mbarrier.try_wait.parity.acquire.cta.shared::cta.b64 p, [%1], %2, 0x989680;\n\t"
            "selp.b32 %0,1,0,p;\n\t}"
            : "=r"(done) : "r"(a), "r"(ph) : "memory");
    }
}

template<int E>
__device__ __forceinline__ float elemf(const float4 (&v)[3]) {
    constexpr int c = E >> 2;
    constexpr int m = E & 3;
    if constexpr (m == 0) return v[c].x;
    else if constexpr (m == 1) return v[c].y;
    else if constexpr (m == 2) return v[c].z;
    else return v[c].w;
}

template<int S>
__device__ __forceinline__ float run8(float s,
    const float4 (&vz)[3], const float4 (&va0)[3], const float4 (&va1)[3],
    const float4 (&vb0)[3], const float4 (&vb1)[3], const float4 (&vg)[3],
    float (&o)[8])
{
#define ONE(J)                                                         \
    {                                                                  \
        float a0 = fmaf(elemf<S+J>(va0), 0.10f, 0.05f);                \
        float a1 = fmaf(elemf<S+J>(va1), 0.20f, 0.10f);                \
        float b0 = elemf<S+J>(vb0) * 0.05f;                            \
        float b1 = elemf<S+J>(vb1) * 0.10f;                            \
        float g  = fmaf(elemf<S+J>(vg), 0.20f, 0.80f);                 \
        float zt = elemf<S+J>(vz) * SQRT_DT;                           \
        float base = fmaf(a1, fmaxf(s, 0.0f), a0);                     \
        s = fmaf(fmaf(b1, s, b0), DT_F, s) + __powf(base, g) * zt;     \
        o[J] = s;                                                      \
    }
    ONE(0) ONE(1) ONE(2) ONE(3) ONE(4) ONE(5) ONE(6) ONE(7)
#undef ONE
    return s;
}

__global__ void __launch_bounds__(160, 2)
gad_kernel(const float* __restrict__ Z,
           const float* __restrict__ Ua0,
           const float* __restrict__ Ua1,
           const float* __restrict__ Ub0,
           const float* __restrict__ Ub1,
           const float* __restrict__ Ug,
           float* __restrict__ out)
{
    extern __shared__ float smem[];
    const int tid = threadIdx.x;
    const int pB  = blockIdx.x * NROWS;
    const unsigned sb = (unsigned)__cvta_generic_to_shared(smem);
    // barriers: full[s] = sb + s*16, empty[s] = sb + s*16 + 8
    if (tid == 0) {
        #pragma unroll
        for (int s = 0; s < STAGES; ++s) {
            mbar_init(sb + s * 16,     32);   // full: 32 producer lanes
            mbar_init(sb + s * 16 + 8, 128);  // empty: 128 consumer threads
        }
    }
    __syncthreads();

    float* data = smem + DATA_OFF;
    const unsigned dbase = sb + DATA_OFF * 4u;

    if (tid >= 128) {
        // ===================== producer warp =====================
        const int lane = tid - 128;
        int ps = 0, pph = 1;
        for (int k = 0; k < NTILES; ++k) {
            const unsigned ful = sb + ps * 16;
            const unsigned emp = ful + 8;
            mbar_wait(emp, pph);
            const unsigned stage = dbase + (unsigned)(ps * BUFF) * 4u;
            const int t0 = 1 + k * TW;
            if (k < 30) {
                #pragma unroll
                for (int i = 0; i < 12; ++i) {
                    const int c    = lane + 32 * i;      // 0..383
                    const int row  = c / 3;
                    const int kk   = c - row * 3;
                    const int slot = ((row & 3) << 5) | (row >> 2);
                    const int slack = (t0 - row) & 3;
                    const int gi = (pB + row) * TSTEPS + t0 - slack + kk * 4;
                    const unsigned d = stage + (unsigned)(slot * RW + kk * 4) * 4u;
                    cp16(d + 0u * (ARRF * 4), Z   + gi);
                    cp16(d + 1u * (ARRF * 4), Ua0 + gi);
                    cp16(d + 2u * (ARRF * 4), Ua1 + gi);
                    cp16(d + 3u * (ARRF * 4), Ub0 + gi);
                    cp16(d + 4u * (ARRF * 4), Ub1 + gi);
                    cp16(d + 5u * (ARRF * 4), Ug  + gi);
                }
            } else {
                const int w = min(TW, TSTEPS - t0);
                for (int idx = lane; idx < NROWS * w; idx += 32) {
                    const int row  = idx / w;
                    const int j    = idx - row * w;
                    const int slot = ((row & 3) << 5) | (row >> 2);
                    const int slack = (t0 - row) & 3;
                    const int gi = (pB + row) * TSTEPS + t0 + j;
                    const unsigned d = stage + (unsigned)(slot * RW + slack + j) * 4u;
                    cp4(d + 0u * (ARRF * 4), Z   + gi);
                    cp4(d + 1u * (ARRF * 4), Ua0 + gi);
                    cp4(d + 2u * (ARRF * 4), Ua1 + gi);
                    cp4(d + 3u * (ARRF * 4), Ub0 + gi);
                    cp4(d + 4u * (ARRF * 4), Ub1 + gi);
                    cp4(d + 5u * (ARRF * 4), Ug  + gi);
                }
            }
            cp_arrive_noinc(ful);   // arrive (no count bump) when copies land
            if (++ps == STAGES) { ps = 0; pph ^= 1; }
        }
    } else {
        // ===================== consumer warps =====================
        const int w32  = tid >> 5;          // warp id 0..3
        const int lane = tid & 31;
        const int r    = 4 * lane + w32;    // my path row (slack-uniform warps)
        const int slot = tid;               // smem slot = tid (48B lane stride)
        const int col  = lane & 7;          // writeback role
        const int rg   = lane >> 3;

        out[(pB + r) * TSTEPS] = S0_F;      // column 0 = S0
        float s = S0_F;
        int cs = 0, cph = 0;

        for (int k = 0; k < NTILES; ++k) {
            const unsigned ful = sb + cs * 16;
            const unsigned emp = ful + 8;
            mbar_wait(ful, cph);

            float* B = data + cs * BUFF;
            const int t0 = 1 + k * TW;
            const int wv = min(TW, TSTEPS - t0);
            const int s4 = (t0 - w32) & 3;      // warp-uniform slack

            if (k < 31) {
                float4 vz[3], va0[3], va1[3], vb0[3], vb1[3], vg[3];
                const float4* p = reinterpret_cast<const float4*>(B) + slot * 3;
                const int A4 = ARRF / 4;        // 384 float4 per array
                #pragma unroll
                for (int c = 0; c < 3; ++c) {
                    vz[c]  = p[0 * A4 + c];
                    va0[c] = p[1 * A4 + c];
                    va1[c] = p[2 * A4 + c];
                    vb0[c] = p[3 * A4 + c];
                    vb1[c] = p[4 * A4 + c];
                    vg[c]  = p[5 * A4 + c];
                }
                float o[8];
                switch (s4) {   // warp-uniform: exactly one case executes
                    case 0: s = run8<0>(s, vz, va0, va1, vb0, vb1, vg, o); break;
                    case 1: s = run8<1>(s, vz, va0, va1, vb0, vb1, vg, o); break;
                    case 2: s = run8<2>(s, vz, va0, va1, vb0, vb1, vg, o); break;
                    default: s = run8<3>(s, vz, va0, va1, vb0, vb1, vg, o); break;
                }
                float4* q = reinterpret_cast<float4*>(B) + slot * 3;
                q[0] = make_float4(o[0], o[1], o[2], o[3]);
                q[1] = make_float4(o[4], o[5], o[6], o[7]);
            } else {
                // last tile (w=2): scalar path
                for (int j = 0; j < wv; ++j) {
                    const int si = slot * RW + s4 + j;
                    float a0 = fmaf(B[1 * ARRF + si], 0.10f, 0.05f);
                    float a1 = fmaf(B[2 * ARRF + si], 0.20f, 0.10f);
                    float b0 = B[3 * ARRF + si] * 0.05f;
                    float b1 = B[4 * ARRF + si] * 0.10f;
                    float g  = fmaf(B[5 * ARRF + si], 0.20f, 0.80f);
                    float zt = B[si] * SQRT_DT;
                    float base = fmaf(a1, fmaxf(s, 0.0f), a0);
                    s = fmaf(fmaf(b1, s, b0), DT_F, s) + __powf(base, g) * zt;
                    B[slot * RW + j] = s;
                }
            }

            __syncwarp();
            // warp-local transposed writeback of this warp's 32 rows
            if (col < wv) {
                #pragma unroll
                for (int ii = 0; ii < 8; ++ii) {
                    const int li  = rg * 8 + ii;          // lane index 0..31
                    const int row = 4 * li + w32;
                    out[(pB + row) * TSTEPS + t0 + col] =
                        B[(w32 * 32 + li) * RW + col];
                }
            }
            __syncwarp();
            mbar_arrive(emp);   // per-thread; own reads are done
            if (++cs == STAGES) { cs = 0; cph ^= 1; }
        }
    }
}

extern "C" void kernel_launch(void* const* d_in, const int* in_sizes, int n_in,
                              void* d_out, int out_size)
{
    const float* Z   = (const float*)d_in[0];
    const float* Ua0 = (const float*)d_in[1];
    const float* Ua1 = (const float*)d_in[2];
    const float* Ub0 = (const float*)d_in[3];
    const float* Ub1 = (const float*)d_in[4];
    const float* Ug  = (const float*)d_in[5];
    float* out = (float*)d_out;

    const int N = in_sizes[0] / TSTEPS;             // 131072
    const int blocks = (N + NROWS - 1) / NROWS;     // 1024

    const size_t smem = (size_t)(DATA_OFF + STAGES * BUFF) * sizeof(float); // 110848 B
    cudaFuncSetAttribute(gad_kernel, cudaFuncAttributeMaxDynamicSharedMemorySize, (int)smem);

    gad_kernel<<<blocks, 160, smem>>>(Z, Ua0, Ua1, Ub0, Ub1, Ug, out);
}

// round 8
// speedup vs baseline: 3.0366x; 1.2708x over previous
#include <cuda_runtime.h>
#include <cstdint>

// path_generator_GAD  (N=131072 paths, T=251)
// s' = s + (b0+b1*s)*dt + (a0+a1*max(s,0))^g * Z*sqrt(dt)
//
// R8 = R7 with TW 8->16 (RW 12->20): ~35-40% fewer L1TEX wavefronts
// (80B windows span 1.5 lines vs 2x1.25 for two 48B windows), half the
// tile count, 1.25x over-read (was 1.5x). 184KB smem -> 1 block/SM; the
// 3-stage decoupled ring keeps L1TEX fed despite 5 warps/SM.

#define TSTEPS  251
#define DT_F    0.004f
#define SQRT_DT 0.063245553203367586f
#define S0_F    100.0f
#define TW      16
#define RW      20                  // floats per row slot (16B multiple)
#define CHUNKS  5                   // RW/4 16B chunks per row
#define NROWS   128
#define NTILES  16                  // ceil(250/16)
#define STAGES  3
#define ARRF    (NROWS * RW)        // 2560 floats per array tile
#define BUFF    (6 * ARRF)          // 15360 floats per stage
#define DATA_OFF 64                 // floats reserved for barriers

__device__ __forceinline__ void cp16(unsigned sa, const float* g) {
    asm volatile("cp.async.cg.shared.global [%0], [%1], 16;" :: "r"(sa), "l"(g));
}
__device__ __forceinline__ void cp4(unsigned sa, const float* g) {
    asm volatile("cp.async.ca.shared.global [%0], [%1], 4;" :: "r"(sa), "l"(g));
}
__device__ __forceinline__ void mbar_init(unsigned a, unsigned cnt) {
    asm volatile("mbarrier.init.shared.b64 [%0], %1;" :: "r"(a), "r"(cnt));
}
__device__ __forceinline__ void mbar_arrive(unsigned a) {
    asm volatile("mbarrier.arrive.shared.b64 _, [%0];" :: "r"(a) : "memory");
}
__device__ __forceinline__ void cp_arrive_noinc(unsigned a) {
    asm volatile("cp.async.mbarrier.arrive.noinc.shared.b64 [%0];" :: "r"(a) : "memory");
}
__device__ __forceinline__ void mbar_wait(unsigned a, unsigned ph) {
    unsigned done;
    asm volatile(
        "{\n\t.reg .pred p;\n\t"
        "mbarrier.try_wait.parity.acquire.cta.shared::cta.b64 p, [%1], %2;\n\t"
        "selp.b32 %0,1,0,p;\n\t}"
        : "=r"(done) : "r"(a), "r"(ph) : "memory");
    while (!done) {
        asm volatile(
            "{\n\t.reg .pred p;\n\t"
            "mbarrier.try_wait.parity.acquire.cta.shared::cta.b64 p, [%1], %2, 0x989680;\n\t"
            "selp.b32 %0,1,0,p;\n\t}"
            : "=r"(done) : "r"(a), "r"(ph) : "memory");
    }
}

template<int E>
__device__ __forceinline__ float elemf(const float4 (&v)[CHUNKS]) {
    constexpr int c = E >> 2;
    constexpr int m = E & 3;
    if constexpr (m == 0) return v[c].x;
    else if constexpr (m == 1) return v[c].y;
    else if constexpr (m == 2) return v[c].z;
    else return v[c].w;
}

template<int S>
__device__ __forceinline__ float run16(float s,
    const float4 (&vz)[CHUNKS], const float4 (&va0)[CHUNKS],
    const float4 (&va1)[CHUNKS], const float4 (&vb0)[CHUNKS],
    const float4 (&vb1)[CHUNKS], const float4 (&vg)[CHUNKS],
    float (&o)[TW])
{
#define ONE(J)                                                         \
    {                                                                  \
        float a0 = fmaf(elemf<S+J>(va0), 0.10f, 0.05f);                \
        float a1 = fmaf(elemf<S+J>(va1), 0.20f, 0.10f);                \
        float b0 = elemf<S+J>(vb0) * 0.05f;                            \
        float b1 = elemf<S+J>(vb1) * 0.10f;                            \
        float g  = fmaf(elemf<S+J>(vg), 0.20f, 0.80f);                 \
        float zt = elemf<S+J>(vz) * SQRT_DT;                           \
        float base = fmaf(a1, fmaxf(s, 0.0f), a0);                     \
        s = fmaf(fmaf(b1, s, b0), DT_F, s) + __powf(base, g) * zt;     \
        o[J] = s;                                                      \
    }
    ONE(0)  ONE(1)  ONE(2)  ONE(3)  ONE(4)  ONE(5)  ONE(6)  ONE(7)
    ONE(8)  ONE(9)  ONE(10) ONE(11) ONE(12) ONE(13) ONE(14) ONE(15)
#undef ONE
    return s;
}

__global__ void __launch_bounds__(160, 1)
gad_kernel(const float* __restrict__ Z,
           const float* __restrict__ Ua0,
           const float* __restrict__ Ua1,
           const float* __restrict__ Ub0,
           const float* __restrict__ Ub1,
           const float* __restrict__ Ug,
           float* __restrict__ out)
{
    extern __shared__ float smem[];
    const int tid = threadIdx.x;
    const int pB  = blockIdx.x * NROWS;
    const unsigned sb = (unsigned)__cvta_generic_to_shared(smem);
    if (tid == 0) {
        #pragma unroll
        for (int s = 0; s < STAGES; ++s) {
            mbar_init(sb + s * 16,     32);   // full: 32 producer lanes
            mbar_init(sb + s * 16 + 8, 128);  // empty: 128 consumer threads
        }
    }
    __syncthreads();

    float* data = smem + DATA_OFF;
    const unsigned dbase = sb + DATA_OFF * 4u;

    if (tid >= 128) {
        // ===================== producer warp =====================
        const int lane = tid - 128;
        int ps = 0, pph = 1;
        for (int k = 0; k < NTILES; ++k) {
            const unsigned ful = sb + ps * 16;
            const unsigned emp = ful + 8;
            mbar_wait(emp, pph);
            const unsigned stage = dbase + (unsigned)(ps * BUFF) * 4u;
            const int t0 = 1 + k * TW;
            if (k < NTILES - 1) {
                // 128 rows x 5 chunks x 6 arrays / 32 lanes = 120 cp16/lane
                #pragma unroll
                for (int i = 0; i < 20; ++i) {
                    const int c    = lane + 32 * i;      // 0..639
                    const int row  = c / CHUNKS;
                    const int kk   = c - row * CHUNKS;   // 0..4
                    const int slot = ((row & 3) << 5) | (row >> 2);
                    const int slack = (t0 - row) & 3;
                    const int gi = (pB + row) * TSTEPS + t0 - slack + kk * 4;
                    const unsigned d = stage + (unsigned)(slot * RW + kk * 4) * 4u;
                    cp16(d + 0u * (ARRF * 4), Z   + gi);
                    cp16(d + 1u * (ARRF * 4), Ua0 + gi);
                    cp16(d + 2u * (ARRF * 4), Ua1 + gi);
                    cp16(d + 3u * (ARRF * 4), Ub0 + gi);
                    cp16(d + 4u * (ARRF * 4), Ub1 + gi);
                    cp16(d + 5u * (ARRF * 4), Ug  + gi);
                }
            } else {
                // last tile (w=10): exact 4B copies (no over-read past end)
                const int w = TSTEPS - t0;               // 10
                for (int idx = lane; idx < NROWS * w; idx += 32) {
                    const int row  = idx / w;
                    const int j    = idx - row * w;
                    const int slot = ((row & 3) << 5) | (row >> 2);
                    const int slack = (t0 - row) & 3;
                    const int gi = (pB + row) * TSTEPS + t0 + j;
                    const unsigned d = stage + (unsigned)(slot * RW + slack + j) * 4u;
                    cp4(d + 0u * (ARRF * 4), Z   + gi);
                    cp4(d + 1u * (ARRF * 4), Ua0 + gi);
                    cp4(d + 2u * (ARRF * 4), Ua1 + gi);
                    cp4(d + 3u * (ARRF * 4), Ub0 + gi);
                    cp4(d + 4u * (ARRF * 4), Ub1 + gi);
                    cp4(d + 5u * (ARRF * 4), Ug  + gi);
                }
            }
            cp_arrive_noinc(ful);
            if (++ps == STAGES) { ps = 0; pph ^= 1; }
        }
    } else {
        // ===================== consumer warps =====================
        const int w32  = tid >> 5;          // warp id 0..3
        const int lane = tid & 31;
        const int r    = 4 * lane + w32;    // my path row (slack-uniform warps)
        const int slot = tid;               // smem slot (80B lane stride)
        const int col  = lane & 15;         // writeback role: 16 cols
        const int rg   = lane >> 4;         // 0/1

        out[(pB + r) * TSTEPS] = S0_F;      // column 0 = S0
        float s = S0_F;
        int cs = 0, cph = 0;

        for (int k = 0; k < NTILES; ++k) {
            const unsigned ful = sb + cs * 16;
            const unsigned emp = ful + 8;
            mbar_wait(ful, cph);

            float* B = data + cs * BUFF;
            const int t0 = 1 + k * TW;
            const int wv = min(TW, TSTEPS - t0);
            const int s4 = (t0 - w32) & 3;      // warp-uniform slack

            if (k < NTILES - 1) {
                float4 vz[CHUNKS], va0[CHUNKS], va1[CHUNKS],
                       vb0[CHUNKS], vb1[CHUNKS], vg[CHUNKS];
                const float4* p = reinterpret_cast<const float4*>(B) + slot * CHUNKS;
                const int A4 = ARRF / 4;        // 640 float4 per array
                #pragma unroll
                for (int c = 0; c < CHUNKS; ++c) {
                    vz[c]  = p[0 * A4 + c];
                    va0[c] = p[1 * A4 + c];
                    va1[c] = p[2 * A4 + c];
                    vb0[c] = p[3 * A4 + c];
                    vb1[c] = p[4 * A4 + c];
                    vg[c]  = p[5 * A4 + c];
                }
                float o[TW];
                switch (s4) {   // warp-uniform: exactly one case executes
                    case 0: s = run16<0>(s, vz, va0, va1, vb0, vb1, vg, o); break;
                    case 1: s = run16<1>(s, vz, va0, va1, vb0, vb1, vg, o); break;
                    case 2: s = run16<2>(s, vz, va0, va1, vb0, vb1, vg, o); break;
                    default: s = run16<3>(s, vz, va0, va1, vb0, vb1, vg, o); break;
                }
                float4* q = reinterpret_cast<float4*>(B) + slot * CHUNKS;
                q[0] = make_float4(o[0],  o[1],  o[2],  o[3]);
                q[1] = make_float4(o[4],  o[5],  o[6],  o[7]);
                q[2] = make_float4(o[8],  o[9],  o[10], o[11]);
                q[3] = make_float4(o[12], o[13], o[14], o[15]);
            } else {
                // last tile (w=10): scalar path
                for (int j = 0; j < wv; ++j) {
                    const int si = slot * RW + s4 + j;
                    float a0 = fmaf(B[1 * ARRF + si], 0.10f, 0.05f);
                    float a1 = fmaf(B[2 * ARRF + si], 0.20f, 0.10f);
                    float b0 = B[3 * ARRF + si] * 0.05f;
                    float b1 = B[4 * ARRF + si] * 0.10f;
                    float g  = fmaf(B[5 * ARRF + si], 0.20f, 0.80f);
                    float zt = B[si] * SQRT_DT;
                    float base = fmaf(a1, fmaxf(s, 0.0f), a0);
                    s = fmaf(fmaf(b1, s, b0), DT_F, s) + __powf(base, g) * zt;
                    B[slot * RW + j] = s;
                }
            }

            __syncwarp();
            // warp-local transposed writeback of this warp's 32 rows
            if (col < wv) {
                #pragma unroll
                for (int ii = 0; ii < 16; ++ii) {
                    const int li  = rg * 16 + ii;         // 0..31
                    const int row = 4 * li + w32;
                    out[(pB + row) * TSTEPS + t0 + col] =
                        B[(w32 * 32 + li) * RW + col];
                }
            }
            __syncwarp();
            mbar_arrive(emp);
            if (++cs == STAGES) { cs = 0; cph ^= 1; }
        }
    }
}

extern "C" void kernel_launch(void* const* d_in, const int* in_sizes, int n_in,
                              void* d_out, int out_size)
{
    const float* Z   = (const float*)d_in[0];
    const float* Ua0 = (const float*)d_in[1];
    const float* Ua1 = (const float*)d_in[2];
    const float* Ub0 = (const float*)d_in[3];
    const float* Ub1 = (const float*)d_in[4];
    const float* Ug  = (const float*)d_in[5];
    float* out = (float*)d_out;

    const int N = in_sizes[0] / TSTEPS;             // 131072
    const int blocks = (N + NROWS - 1) / NROWS;     // 1024

    const size_t smem = (size_t)(DATA_OFF + STAGES * BUFF) * sizeof(float); // 184576 B
    cudaFuncSetAttribute(gad_kernel, cudaFuncAttributeMaxDynamicSharedMemorySize, (int)smem);

    gad_kernel<<<blocks, 160, smem>>>(Z, Ua0, Ua1, Ub0, Ub1, Ug, out);
}

// round 9
// speedup vs baseline: 3.1201x; 1.0275x over previous
#include <cuda_runtime.h>
#include <cstdint>

// path_generator_GAD  (N=131072 paths, T=251)
// s' = s + (b0+b1*s)*dt + (a0+a1*max(s,0))^g * Z*sqrt(dt)
//
// R9 = R8 + second producer warp (192 threads): doubles LDGSTS issue
// bandwidth (~48 -> ~96 B/cyc/SM) and in-flight depth; full barrier
// count 32 -> 64. Consumer side unchanged (warp-uniform slack,
// conflict-free LDS.128, smem-staged coalesced writeback).

#define TSTEPS  251
#define DT_F    0.004f
#define SQRT_DT 0.063245553203367586f
#define S0_F    100.0f
#define TW      16
#define RW      20                  // floats per row slot (16B multiple)
#define CHUNKS  5                   // RW/4 16B chunks per row
#define NROWS   128
#define NTILES  16                  // ceil(250/16)
#define STAGES  3
#define PLANES  64                  // producer lanes (2 warps)
#define ARRF    (NROWS * RW)        // 2560 floats per array tile
#define BUFF    (6 * ARRF)          // 15360 floats per stage
#define DATA_OFF 64                 // floats reserved for barriers

__device__ __forceinline__ void cp16(unsigned sa, const float* g) {
    asm volatile("cp.async.cg.shared.global [%0], [%1], 16;" :: "r"(sa), "l"(g));
}
__device__ __forceinline__ void cp4(unsigned sa, const float* g) {
    asm volatile("cp.async.ca.shared.global [%0], [%1], 4;" :: "r"(sa), "l"(g));
}
__device__ __forceinline__ void mbar_init(unsigned a, unsigned cnt) {
    asm volatile("mbarrier.init.shared.b64 [%0], %1;" :: "r"(a), "r"(cnt));
}
__device__ __forceinline__ void mbar_arrive(unsigned a) {
    asm volatile("mbarrier.arrive.shared.b64 _, [%0];" :: "r"(a) : "memory");
}
__device__ __forceinline__ void cp_arrive_noinc(unsigned a) {
    asm volatile("cp.async.mbarrier.arrive.noinc.shared.b64 [%0];" :: "r"(a) : "memory");
}
__device__ __forceinline__ void mbar_wait(unsigned a, unsigned ph) {
    unsigned done;
    asm volatile(
        "{\n\t.reg .pred p;\n\t"
        "mbarrier.try_wait.parity.acquire.cta.shared::cta.b64 p, [%1], %2;\n\t"
        "selp.b32 %0,1,0,p;\n\t}"
        : "=r"(done) : "r"(a), "r"(ph) : "memory");
    while (!done) {
        asm volatile(
            "{\n\t.reg .pred p;\n\t"
            "mbarrier.try_wait.parity.acquire.cta.shared::cta.b64 p, [%1], %2, 0x989680;\n\t"
            "selp.b32 %0,1,0,p;\n\t}"
            : "=r"(done) : "r"(a), "r"(ph) : "memory");
    }
}

template<int E>
__device__ __forceinline__ float elemf(const float4 (&v)[CHUNKS]) {
    constexpr int c = E >> 2;
    constexpr int m = E & 3;
    if constexpr (m == 0) return v[c].x;
    else if constexpr (m == 1) return v[c].y;
    else if constexpr (m == 2) return v[c].z;
    else return v[c].w;
}

template<int S>
__device__ __forceinline__ float run16(float s,
    const float4 (&vz)[CHUNKS], const float4 (&va0)[CHUNKS],
    const float4 (&va1)[CHUNKS], const float4 (&vb0)[CHUNKS],
    const float4 (&vb1)[CHUNKS], const float4 (&vg)[CHUNKS],
    float (&o)[TW])
{
#define ONE(J)                                                         \
    {                                                                  \
        float a0 = fmaf(elemf<S+J>(va0), 0.10f, 0.05f);                \
        float a1 = fmaf(elemf<S+J>(va1), 0.20f, 0.10f);                \
        float b0 = elemf<S+J>(vb0) * 0.05f;                            \
        float b1 = elemf<S+J>(vb1) * 0.10f;                            \
        float g  = fmaf(elemf<S+J>(vg), 0.20f, 0.80f);                 \
        float zt = elemf<S+J>(vz) * SQRT_DT;                           \
        float base = fmaf(a1, fmaxf(s, 0.0f), a0);                     \
        s = fmaf(fmaf(b1, s, b0), DT_F, s) + __powf(base, g) * zt;     \
        o[J] = s;                                                      \
    }
    ONE(0)  ONE(1)  ONE(2)  ONE(3)  ONE(4)  ONE(5)  ONE(6)  ONE(7)
    ONE(8)  ONE(9)  ONE(10) ONE(11) ONE(12) ONE(13) ONE(14) ONE(15)
#undef ONE
    return s;
}

__global__ void __launch_bounds__(192, 1)
gad_kernel(const float* __restrict__ Z,
           const float* __restrict__ Ua0,
           const float* __restrict__ Ua1,
           const float* __restrict__ Ub0,
           const float* __restrict__ Ub1,
           const float* __restrict__ Ug,
           float* __restrict__ out)
{
    extern __shared__ float smem[];
    const int tid = threadIdx.x;
    const int pB  = blockIdx.x * NROWS;
    const unsigned sb = (unsigned)__cvta_generic_to_shared(smem);
    if (tid == 0) {
        #pragma unroll
        for (int s = 0; s < STAGES; ++s) {
            mbar_init(sb + s * 16,     PLANES);  // full: 64 producer lanes
            mbar_init(sb + s * 16 + 8, 128);     // empty: 128 consumer threads
        }
    }
    __syncthreads();

    float* data = smem + DATA_OFF;
    const unsigned dbase = sb + DATA_OFF * 4u;

    if (tid >= 128) {
        // ================= producer warps (2) =================
        const int lane = tid - 128;              // 0..63
        int ps = 0, pph = 1;
        for (int k = 0; k < NTILES; ++k) {
            const unsigned ful = sb + ps * 16;
            const unsigned emp = ful + 8;
            mbar_wait(emp, pph);
            const unsigned stage = dbase + (unsigned)(ps * BUFF) * 4u;
            const int t0 = 1 + k * TW;
            if (k < NTILES - 1) {
                // 128 rows x 5 chunks x 6 arrays / 64 lanes = 60 cp16/lane
                #pragma unroll
                for (int i = 0; i < 10; ++i) {
                    const int c    = lane + PLANES * i;  // 0..639
                    const int row  = c / CHUNKS;
                    const int kk   = c - row * CHUNKS;   // 0..4
                    const int slot = ((row & 3) << 5) | (row >> 2);
                    const int slack = (t0 - row) & 3;
                    const int gi = (pB + row) * TSTEPS + t0 - slack + kk * 4;
                    const unsigned d = stage + (unsigned)(slot * RW + kk * 4) * 4u;
                    cp16(d + 0u * (ARRF * 4), Z   + gi);
                    cp16(d + 1u * (ARRF * 4), Ua0 + gi);
                    cp16(d + 2u * (ARRF * 4), Ua1 + gi);
                    cp16(d + 3u * (ARRF * 4), Ub0 + gi);
                    cp16(d + 4u * (ARRF * 4), Ub1 + gi);
                    cp16(d + 5u * (ARRF * 4), Ug  + gi);
                }
            } else {
                // last tile (w=10): exact 4B copies (no over-read past end)
                const int w = TSTEPS - t0;               // 10
                for (int idx = lane; idx < NROWS * w; idx += PLANES) {
                    const int row  = idx / w;
                    const int j    = idx - row * w;
                    const int slot = ((row & 3) << 5) | (row >> 2);
                    const int slack = (t0 - row) & 3;
                    const int gi = (pB + row) * TSTEPS + t0 + j;
                    const unsigned d = stage + (unsigned)(slot * RW + slack + j) * 4u;
                    cp4(d + 0u * (ARRF * 4), Z   + gi);
                    cp4(d + 1u * (ARRF * 4), Ua0 + gi);
                    cp4(d + 2u * (ARRF * 4), Ua1 + gi);
                    cp4(d + 3u * (ARRF * 4), Ub0 + gi);
                    cp4(d + 4u * (ARRF * 4), Ub1 + gi);
                    cp4(d + 5u * (ARRF * 4), Ug  + gi);
                }
            }
            cp_arrive_noinc(ful);
            if (++ps == STAGES) { ps = 0; pph ^= 1; }
        }
    } else {
        // ===================== consumer warps =====================
        const int w32  = tid >> 5;          // warp id 0..3
        const int lane = tid & 31;
        const int r    = 4 * lane + w32;    // my path row (slack-uniform warps)
        const int slot = tid;               // smem slot (80B lane stride)
        const int col  = lane & 15;         // writeback role: 16 cols
        const int rg   = lane >> 4;         // 0/1

        out[(pB + r) * TSTEPS] = S0_F;      // column 0 = S0
        float s = S0_F;
        int cs = 0, cph = 0;

        for (int k = 0; k < NTILES; ++k) {
            const unsigned ful = sb + cs * 16;
            const unsigned emp = ful + 8;
            mbar_wait(ful, cph);

            float* B = data + cs * BUFF;
            const int t0 = 1 + k * TW;
            const int wv = min(TW, TSTEPS - t0);
            const int s4 = (t0 - w32) & 3;      // warp-uniform slack

            if (k < NTILES - 1) {
                float4 vz[CHUNKS], va0[CHUNKS], va1[CHUNKS],
                       vb0[CHUNKS], vb1[CHUNKS], vg[CHUNKS];
                const float4* p = reinterpret_cast<const float4*>(B) + slot * CHUNKS;
                const int A4 = ARRF / 4;        // 640 float4 per array
                #pragma unroll
                for (int c = 0; c < CHUNKS; ++c) {
                    vz[c]  = p[0 * A4 + c];
                    va0[c] = p[1 * A4 + c];
                    va1[c] = p[2 * A4 + c];
                    vb0[c] = p[3 * A4 + c];
                    vb1[c] = p[4 * A4 + c];
                    vg[c]  = p[5 * A4 + c];
                }
                float o[TW];
                switch (s4) {   // warp-uniform: exactly one case executes
                    case 0: s = run16<0>(s, vz, va0, va1, vb0, vb1, vg, o); break;
                    case 1: s = run16<1>(s, vz, va0, va1, vb0, vb1, vg, o); break;
                    case 2: s = run16<2>(s, vz, va0, va1, vb0, vb1, vg, o); break;
                    default: s = run16<3>(s, vz, va0, va1, vb0, vb1, vg, o); break;
                }
                float4* q = reinterpret_cast<float4*>(B) + slot * CHUNKS;
                q[0] = make_float4(o[0],  o[1],  o[2],  o[3]);
                q[1] = make_float4(o[4],  o[5],  o[6],  o[7]);
                q[2] = make_float4(o[8],  o[9],  o[10], o[11]);
                q[3] = make_float4(o[12], o[13], o[14], o[15]);
            } else {
                // last tile (w=10): scalar path
                for (int j = 0; j < wv; ++j) {
                    const int si = slot * RW + s4 + j;
                    float a0 = fmaf(B[1 * ARRF + si], 0.10f, 0.05f);
                    float a1 = fmaf(B[2 * ARRF + si], 0.20f, 0.10f);
                    float b0 = B[3 * ARRF + si] * 0.05f;
                    float b1 = B[4 * ARRF + si] * 0.10f;
                    float g  = fmaf(B[5 * ARRF + si], 0.20f, 0.80f);
                    float zt = B[si] * SQRT_DT;
                    float base = fmaf(a1, fmaxf(s, 0.0f), a0);
                    s = fmaf(fmaf(b1, s, b0), DT_F, s) + __powf(base, g) * zt;
                    B[slot * RW + j] = s;
                }
            }

            __syncwarp();
            // warp-local transposed writeback of this warp's 32 rows
            if (col < wv) {
                #pragma unroll
                for (int ii = 0; ii < 16; ++ii) {
                    const int li  = rg * 16 + ii;         // 0..31
                    const int row = 4 * li + w32;
                    out[(pB + row) * TSTEPS + t0 + col] =
                        B[(w32 * 32 + li) * RW + col];
                }
            }
            __syncwarp();
            mbar_arrive(emp);
            if (++cs == STAGES) { cs = 0; cph ^= 1; }
        }
    }
}

extern "C" void kernel_launch(void* const* d_in, const int* in_sizes, int n_in,
                              void* d_out, int out_size)
{
    const float* Z   = (const float*)d_in[0];
    const float* Ua0 = (const float*)d_in[1];
    const float* Ua1 = (const float*)d_in[2];
    const float* Ub0 = (const float*)d_in[3];
    const float* Ub1 = (const float*)d_in[4];
    const float* Ug  = (const float*)d_in[5];
    float* out = (float*)d_out;

    const int N = in_sizes[0] / TSTEPS;             // 131072
    const int blocks = (N + NROWS - 1) / NROWS;     // 1024

    const size_t smem = (size_t)(DATA_OFF + STAGES * BUFF) * sizeof(float); // 184576 B
    cudaFuncSetAttribute(gad_kernel, cudaFuncAttributeMaxDynamicSharedMemorySize, (int)smem);

    gad_kernel<<<blocks, 192, smem>>>(Z, Ua0, Ua1, Ub0, Ub1, Ug, out);
}